// round 6
// baseline (speedup 1.0000x reference)
#include <cuda_runtime.h>
#include <cstdint>

#define B_  16
#define L_  64
#define F_  60
#define D_  256
#define U_  600
#define V_  10000
#define E_  7
#define NEGF (-1e9f)

// Scratch (device globals)
__device__ float g_wn[1024 * 256];
__device__ float g_un[600 * 256];
__device__ float g_sim[2 * 1024 * 600];      // two K-halves, summed in phaseB
__device__ uint4 g_segB[7 * V_ * 2];         // length-bucketed vocab
__device__ int   g_cnt[8];                   // bucket counts (zero at steady state)
__device__ unsigned long long g_keys[16];
__device__ unsigned g_done;

// ---- f32x2 helpers ----
__device__ __forceinline__ unsigned long long pk2dup(float a) {
    unsigned long long r; unsigned ai = __float_as_uint(a);
    asm("mov.b64 %0, {%1, %1};" : "=l"(r) : "r"(ai));
    return r;
}
__device__ __forceinline__ void ffma2(unsigned long long& d, unsigned long long a, unsigned long long b) {
    asm("fma.rn.f32x2 %0, %1, %2, %0;" : "+l"(d) : "l"(a), "l"(b));
}
__device__ __forceinline__ void fadd2(unsigned long long& d, unsigned long long a) {
    asm("add.rn.f32x2 %0, %0, %1;" : "+l"(d) : "l"(a));
}
__device__ __forceinline__ void fmul2(unsigned long long& d, unsigned long long a) {
    asm("mul.rn.f32x2 %0, %0, %1;" : "+l"(d) : "l"(a));
}
__device__ __forceinline__ float2 unpk2(unsigned long long a) {
    unsigned lo, hi;
    asm("mov.b64 {%0, %1}, %2;" : "=r"(lo), "=r"(hi) : "l"(a));
    return make_float2(__uint_as_float(lo), __uint_as_float(hi));
}

__device__ __forceinline__ unsigned f2mono(float f) {
    unsigned b = __float_as_uint(f);
    return (b & 0x80000000u) ? ~b : (b | 0x80000000u);
}
__device__ __forceinline__ unsigned long long pack_key(float s, int f, int v) {
    return ((unsigned long long)f2mono(s) << 23)
         | ((unsigned long long)(511 - f) << 14)
         | (unsigned long long)(16383 - v);
}

// ---------------------------------------------------------------------------
// Kernel 1 (setup): embed 16 rows/block with smem-staged W; bucket vocab.
//   blocks   0..63  : word rows   (64*16 = 1024)
//   blocks  64..101 : unit rows   (38*16 >= 600)
//   blocks 102..141 : vocab bucketing (256 words each)
// ---------------------------------------------------------------------------
#define WB_ 64
#define UB_ 38
#define PBK_ 40
#define SETUP_GRID (WB_ + UB_ + PBK_)                       // 142
#define SETUP_SMEM ((15360 + 960 + 128 + 16) * 4)           // 65856 B

__global__ void __launch_bounds__(256) k_setup(const float* __restrict__ x,
                                               const float* __restrict__ uf,
                                               const float* __restrict__ W,
                                               const int* __restrict__ segs,
                                               const int* __restrict__ vlen) {
    extern __shared__ float SS[];
    int blk = blockIdx.x;
    int d = threadIdx.x;
    if (blk < WB_ + UB_) {
        float* Wsh   = SS;             // 60*256
        float* featT = SS + 15360;     // 60*16 (transposed: [f][r])
        float* spart = SS + 16320;     // 16*8
        float* sinv  = SS + 16448;     // 16
        bool isWord = blk < WB_;
        int r0 = isWord ? blk * 16 : (blk - WB_) * 16;
        const float* src = isWord ? (x + r0 * F_) : (uf + r0 * F_);
        float* dst = isWord ? (g_wn + r0 * D_) : (g_un + r0 * D_);
        int nvalid = isWord ? 16 : min(16, U_ - r0);
        // stage W (float4, high MLP)
        const float4* W4 = (const float4*)W;
        #pragma unroll
        for (int i = d; i < 3840; i += 256) ((float4*)Wsh)[i] = W4[i];
        // stage transposed feats (pairs of rows adjacent for f32x2)
        for (int i = d; i < 16 * F_; i += 256) {
            int r = i / F_, f = i - r * F_;
            featT[f * 16 + r] = (r < nvalid) ? src[r * F_ + f] : 0.f;
        }
        __syncthreads();
        unsigned long long v2[8];
        #pragma unroll
        for (int p = 0; p < 8; p++) v2[p] = 0ull;
        #pragma unroll 4
        for (int f = 0; f < F_; f++) {
            unsigned long long w2 = pk2dup(Wsh[f * D_ + d]);
            const unsigned long long* fp = (const unsigned long long*)(featT + f * 16);
            #pragma unroll
            for (int p = 0; p < 8; p++) ffma2(v2[p], fp[p], w2);
        }
        float val[16];
        #pragma unroll
        for (int p = 0; p < 8; p++) {
            float2 t = unpk2(v2[p]);
            val[2 * p] = t.x; val[2 * p + 1] = t.y;
        }
        int lane = d & 31, w = d >> 5;
        #pragma unroll
        for (int r = 0; r < 16; r++) {
            float q = val[r] * val[r];
            #pragma unroll
            for (int o = 16; o; o >>= 1) q += __shfl_down_sync(0xffffffffu, q, o);
            if (lane == 0) spart[r * 8 + w] = q;
        }
        __syncthreads();
        if (d < 16) {
            float s = 0.f;
            #pragma unroll
            for (int i = 0; i < 8; i++) s += spart[d * 8 + i];
            sinv[d] = 1.0f / (sqrtf(s) + 1e-8f);
        }
        __syncthreads();
        #pragma unroll
        for (int r = 0; r < 16; r++)
            if (r < nvalid) dst[r * D_ + d] = val[r] * sinv[r];
    } else {
        // ---- bucket vocab by length (warp-aggregated atomic slots) ----
        int pb = blk - (WB_ + UB_);
        int v = pb * 256 + d;
        bool act = v < V_;
        int len = act ? vlen[v] : 11;
        int idx = act ? (len - 4) : 7;
        int lane = d & 31;
        unsigned mask = __match_any_sync(0xffffffffu, idx);
        int leader = __ffs(mask) - 1;
        int prior = __popc(mask & ((1u << lane) - 1));
        int base = 0;
        if (lane == leader) base = atomicAdd(&g_cnt[idx], __popc(mask));
        base = __shfl_sync(mask, base, leader);
        if (act) {
            unsigned w[5];
            #pragma unroll
            for (int p = 0; p < 5; p++) {
                unsigned lo = (unsigned)segs[v * 10 + 2 * p];
                unsigned hi = (unsigned)segs[v * 10 + 2 * p + 1];
                w[p] = (lo & 0xFFFFu) | (hi << 16);
            }
            if (len <= 7) w[3] = (w[3] & 0xFFFFu) | ((unsigned)v << 16);  // v in spare slot
            int slot = idx * V_ + base + prior;
            g_segB[slot * 2]     = make_uint4(w[0], w[1], w[2], w[3]);
            g_segB[slot * 2 + 1] = make_uint4(w[4], (unsigned)v, 0u, 0u);
        }
        if (pb == PBK_ - 1) {   // idle-lane housekeeping
            if (d >= 32 && d < 48) g_keys[d - 32] = pack_key(NEGF, 0, 0);
            if (d == 63) g_done = 0u;
        }
    }
}

// ---------------------------------------------------------------------------
// Kernel 2: sim = wn @ un^T, 64x64 tile, f32x2 FMAs, K split in two halves.
// grid = (10, 16, 2)
// ---------------------------------------------------------------------------
__global__ void __launch_bounds__(256) k_sim_gemm() {
    __shared__ float As[16 * 64];
    __shared__ float Bs[16 * 64];
    int tid = threadIdx.x;
    int n0 = blockIdx.x * 64;
    int m0 = blockIdx.y * 64;
    int kz = blockIdx.z;
    float* dst = g_sim + kz * (1024 * 600);
    int tx = tid & 15, ty = tid >> 4;
    int lm = tid >> 2;
    int lk = (tid & 3) * 4;
    unsigned long long acc2[4][2];
    #pragma unroll
    for (int i = 0; i < 4; i++) { acc2[i][0] = 0ull; acc2[i][1] = 0ull; }
    int kbeg = kz * 128;
    for (int k0 = kbeg; k0 < kbeg + 128; k0 += 16) {
        float4 a = *(const float4*)(g_wn + (m0 + lm) * 256 + k0 + lk);
        float4 bv = make_float4(0.f, 0.f, 0.f, 0.f);
        int n = n0 + lm;
        if (n < U_) bv = *(const float4*)(g_un + n * 256 + k0 + lk);
        __syncthreads();
        As[(lk + 0) * 64 + lm] = a.x;
        As[(lk + 1) * 64 + lm] = a.y;
        As[(lk + 2) * 64 + lm] = a.z;
        As[(lk + 3) * 64 + lm] = a.w;
        Bs[(lk + 0) * 64 + lm] = bv.x;
        Bs[(lk + 1) * 64 + lm] = bv.y;
        Bs[(lk + 2) * 64 + lm] = bv.z;
        Bs[(lk + 3) * 64 + lm] = bv.w;
        __syncthreads();
        #pragma unroll
        for (int kk = 0; kk < 16; kk++) {
            float4 aq = *(const float4*)(As + kk * 64 + ty * 4);
            ulonglong2 bp = *(const ulonglong2*)(Bs + kk * 64 + tx * 4);
            unsigned long long a0 = pk2dup(aq.x), a1 = pk2dup(aq.y);
            unsigned long long a2 = pk2dup(aq.z), a3 = pk2dup(aq.w);
            ffma2(acc2[0][0], a0, bp.x); ffma2(acc2[0][1], a0, bp.y);
            ffma2(acc2[1][0], a1, bp.x); ffma2(acc2[1][1], a1, bp.y);
            ffma2(acc2[2][0], a2, bp.x); ffma2(acc2[2][1], a2, bp.y);
            ffma2(acc2[3][0], a3, bp.x); ffma2(acc2[3][1], a3, bp.y);
        }
    }
    #pragma unroll
    for (int i = 0; i < 4; i++) {
        int m = m0 + ty * 4 + i;
        #pragma unroll
        for (int j2 = 0; j2 < 2; j2++) {
            float2 c = unpk2(acc2[i][j2]);
            int n = n0 + tx * 4 + j2 * 2;
            if (n < U_)     dst[m * U_ + n] = c.x;
            if (n + 1 < U_) dst[m * U_ + n + 1] = c.y;
        }
    }
}

// ---------------------------------------------------------------------------
// Kernel 3 (hot): CTA per (vc, b). Smem holds paired rows:
//   P[u*41 + r] = { sim[b][r][u], sim[b][r+32][u] }   r in 0..40, rows>=64 -> 0
// Lanes = 32 start positions; both 32-l halves accumulated at once via f32x2.
// ---------------------------------------------------------------------------
#define PB_SMEM (600 * 41 * 8)
#define VC_ 9
#define NPART_ (VC_ * 16)       // 144 vocab partitions
#define NCTA_PB (VC_ * 16)      // 144 CTAs

template<int LEN>
__device__ __forceinline__ void scan_bucket(
        const uint4* __restrict__ seg, int lo, int hi,
        const float2* __restrict__ Pl,
        unsigned long long midLo, unsigned long long midHi,
        bool okLo, bool okHi, float inv,
        unsigned long long& bestKey) {
    unsigned long long inv2 = pk2dup(inv);
    #pragma unroll 2
    for (int i = lo; i < hi; i++) {
        uint4 q0 = __ldg(&seg[2 * i]);
        unsigned u89 = 0, vv;
        if (LEN <= 7) {
            vv = q0.w >> 16;
        } else {
            uint4 q1 = __ldg(&seg[2 * i + 1]);
            u89 = q1.x; vv = q1.y;
        }
        unsigned long long acc;
        unsigned u;
        u = q0.x & 0xFFFFu;                 acc = *(const unsigned long long*)(Pl + u * 41 + 0);
        u = q0.x >> 16;                     fadd2(acc, *(const unsigned long long*)(Pl + u * 41 + 1));
        u = q0.y & 0xFFFFu;                 fadd2(acc, *(const unsigned long long*)(Pl + u * 41 + 2));
        u = q0.y >> 16;                     fadd2(acc, *(const unsigned long long*)(Pl + u * 41 + 3));
        if (LEN > 4) { u = q0.z & 0xFFFFu;  fadd2(acc, *(const unsigned long long*)(Pl + u * 41 + 4)); }
        if (LEN > 5) { u = q0.z >> 16;      fadd2(acc, *(const unsigned long long*)(Pl + u * 41 + 5)); }
        if (LEN > 6) { u = q0.w & 0xFFFFu;  fadd2(acc, *(const unsigned long long*)(Pl + u * 41 + 6)); }
        if (LEN > 7) { u = q0.w >> 16;      fadd2(acc, *(const unsigned long long*)(Pl + u * 41 + 7)); }
        if (LEN > 8) { u = u89 & 0xFFFFu;   fadd2(acc, *(const unsigned long long*)(Pl + u * 41 + 8)); }
        if (LEN > 9) { u = u89 >> 16;       fadd2(acc, *(const unsigned long long*)(Pl + u * 41 + 9)); }
        fmul2(acc, inv2);
        float2 s = unpk2(acc);
        unsigned long long vterm = (unsigned long long)(16383u - vv);
        if (okLo) {
            unsigned long long key = ((unsigned long long)f2mono(s.x) << 23) | midLo | vterm;
            if (key > bestKey) bestKey = key;
        }
        if (okHi) {
            unsigned long long key = ((unsigned long long)f2mono(s.y) << 23) | midHi | vterm;
            if (key > bestKey) bestKey = key;
        }
    }
}

__global__ void __launch_bounds__(512, 1) k_phaseB(const int* __restrict__ lengths,
                                                   float* __restrict__ out) {
    extern __shared__ float2 P[];
    __shared__ int cnt_s[8];
    int vc = blockIdx.x;   // 0..8
    int b  = blockIdx.y;   // 0..15
    if (threadIdx.x < 8) cnt_s[threadIdx.x] = g_cnt[threadIdx.x];
    const float* sA = g_sim + b * 64 * U_;
    const float* sB = sA + 1024 * U_;
    for (int i = threadIdx.x; i < U_ * 41; i += 512) {
        int r = i / U_;
        int u = i - r * U_;
        float lo = sA[r * U_ + u] + sB[r * U_ + u];
        float hi = (r < 32) ? (sA[(r + 32) * U_ + u] + sB[(r + 32) * U_ + u]) : 0.f;
        P[u * 41 + r] = make_float2(lo, hi);
    }
    __syncthreads();

    int warp = threadIdx.x >> 5;
    int lane = threadIdx.x & 31;
    int Lb = __ldg(&lengths[b]);
    const float2* Pl = P + lane;
    int part = vc * 16 + warp;
    unsigned long long bestKey = ((unsigned long long)f2mono(NEGF) << 23);

    #define DO_BUCKET(LI, LEN)                                                          \
    if (LEN <= Lb) {                                                                    \
        int n = cnt_s[LI];                                                              \
        int lo = (part * n) / NPART_;                                                   \
        int hi = ((part + 1) * n) / NPART_;                                             \
        bool okLo = lane + LEN <= Lb;                                                   \
        bool okHi = lane + 32 + LEN <= Lb;                                              \
        unsigned long long midLo = ((unsigned long long)(511 - (lane * E_ + LI)) << 14);\
        unsigned long long midHi = ((unsigned long long)(511 - ((lane + 32) * E_ + LI)) << 14);\
        scan_bucket<LEN>(g_segB + LI * (V_ * 2), lo, hi, Pl, midLo, midHi, okLo, okHi,  \
                         1.0f / (float)LEN, bestKey);                                   \
    }
    DO_BUCKET(0, 4) DO_BUCKET(1, 5) DO_BUCKET(2, 6) DO_BUCKET(3, 7)
    DO_BUCKET(4, 8) DO_BUCKET(5, 9) DO_BUCKET(6, 10)
    #undef DO_BUCKET

    #pragma unroll
    for (int o = 16; o; o >>= 1) {
        unsigned long long other = __shfl_down_sync(0xffffffffu, bestKey, o);
        if (other > bestKey) bestKey = other;
    }
    if (lane == 0) atomicMax(&g_keys[b], bestKey);

    // -------- fused epilogue: last CTA decodes + resets bucket counters -----
    __syncthreads();
    __threadfence();
    __shared__ unsigned s_old;
    if (threadIdx.x == 0) s_old = atomicAdd(&g_done, 1u);
    __syncthreads();
    if (s_old == NCTA_PB - 1) {
        int t = threadIdx.x;
        if (t < B_) {
            unsigned long long k2 = atomicAdd(&g_keys[t], 0ull);
            int v = 16383 - (int)(k2 & 0x3FFFull);
            int f = 511 - (int)((k2 >> 14) & 0x1FFull);
            unsigned mono = (unsigned)(k2 >> 23);
            unsigned fb = (mono & 0x80000000u) ? (mono & 0x7FFFFFFFu) : ~mono;
            float score = __uint_as_float(fb);
            int ll = f / E_;
            int e = f - ll * E_;
            out[0 * B_ + t] = score;
            out[1 * B_ + t] = (float)ll;
            out[2 * B_ + t] = (float)(ll + e + 3);
            out[3 * B_ + t] = (score > 0.05f) ? 1.0f : 0.0f;
            out[4 * B_ + t] = (float)v;
        }
        if (t >= 32 && t < 40) g_cnt[t - 32] = 0;   // ready for next replay
    }
}

// ---------------------------------------------------------------------------
extern "C" void kernel_launch(void* const* d_in, const int* in_sizes, int n_in,
                              void* d_out, int out_size) {
    const float* x       = (const float*)d_in[0];
    const float* uf      = (const float*)d_in[1];
    const float* W       = (const float*)d_in[2];
    const int*   lengths = (const int*)d_in[3];
    const int*   segs    = (const int*)d_in[4];
    const int*   vlen    = (const int*)d_in[5];
    float* out = (float*)d_out;

    cudaFuncSetAttribute(k_setup, cudaFuncAttributeMaxDynamicSharedMemorySize, SETUP_SMEM);
    cudaFuncSetAttribute(k_phaseB, cudaFuncAttributeMaxDynamicSharedMemorySize, PB_SMEM);

    k_setup<<<SETUP_GRID, 256, SETUP_SMEM>>>(x, uf, W, segs, vlen);
    k_sim_gemm<<<dim3(10, 16, 2), 256>>>();
    k_phaseB<<<dim3(VC_, B_), 512, PB_SMEM>>>(lengths, out);
}

// round 10
// speedup vs baseline: 1.5301x; 1.5301x over previous
#include <cuda_runtime.h>
#include <cstdint>

#define B_  16
#define L_  64
#define F_  60
#define D_  256
#define U_  600
#define V_  10000
#define E_  7
#define NEGF (-1e9f)

// Scratch (device globals)
__device__ float g_wn[1024 * 256];
__device__ float g_un[600 * 256];
__device__ float g_sim[2 * 1024 * 600];      // two K-halves, summed in phaseB staging
__device__ uint4 g_segB[7 * V_ * 2];         // length-bucketed vocab
__device__ int   g_cnt[8];                   // bucket counts (zeroed by phaseB epilogue)
__device__ unsigned long long g_keys[16];
__device__ unsigned g_done;

// ---- f32x2 helpers ----
__device__ __forceinline__ void ffma2(unsigned long long& d, unsigned long long a, unsigned long long b) {
    asm("fma.rn.f32x2 %0, %1, %2, %0;" : "+l"(d) : "l"(a), "l"(b));
}
__device__ __forceinline__ void fadd2(unsigned long long& d, unsigned long long a) {
    asm("add.rn.f32x2 %0, %0, %1;" : "+l"(d) : "l"(a));
}
__device__ __forceinline__ void fmul2(unsigned long long& d, unsigned long long a) {
    asm("mul.rn.f32x2 %0, %0, %1;" : "+l"(d) : "l"(a));
}
__device__ __forceinline__ unsigned long long pk2dup(float a) {
    unsigned long long r; unsigned ai = __float_as_uint(a);
    asm("mov.b64 %0, {%1, %1};" : "=l"(r) : "r"(ai));
    return r;
}
__device__ __forceinline__ float2 unpk2(unsigned long long a) {
    unsigned lo, hi;
    asm("mov.b64 {%0, %1}, %2;" : "=r"(lo), "=r"(hi) : "l"(a));
    return make_float2(__uint_as_float(lo), __uint_as_float(hi));
}

__device__ __forceinline__ unsigned f2mono(float f) {
    unsigned b = __float_as_uint(f);
    return (b & 0x80000000u) ? ~b : (b | 0x80000000u);
}
__device__ __forceinline__ unsigned long long pack_key(float s, int f, int v) {
    return ((unsigned long long)f2mono(s) << 23)
         | ((unsigned long long)(511 - f) << 14)
         | (unsigned long long)(16383 - v);
}

// ---------------------------------------------------------------------------
// Kernel 1 (setup): embed 4 rows/block (direct W loads, high block count);
// vocab bucketing.
//   blocks   0..255 : word rows  (256*4 = 1024)
//   blocks 256..405 : unit rows  (150*4 = 600)
//   blocks 406..445 : vocab bucketing (256 words each)
// ---------------------------------------------------------------------------
#define WB_ 256
#define UB_ 150
#define PBK_ 40
#define SETUP_GRID (WB_ + UB_ + PBK_)   // 446

__global__ void __launch_bounds__(256) k_setup(const float* __restrict__ x,
                                               const float* __restrict__ uf,
                                               const float* __restrict__ W,
                                               const int* __restrict__ segs,
                                               const int* __restrict__ vlen) {
    int blk = blockIdx.x;
    int d = threadIdx.x;               // 0..255 == D_
    if (blk < WB_ + UB_) {
        __shared__ float feat[4 * F_];
        __shared__ float spart[4 * 8];
        __shared__ float sinv[4];
        bool isWord = blk < WB_;
        int r0 = isWord ? blk * 4 : (blk - WB_) * 4;
        const float* src = isWord ? (x + r0 * F_) : (uf + r0 * F_);
        float* dst = isWord ? (g_wn + r0 * D_) : (g_un + r0 * D_);
        if (d < 4 * F_) feat[d] = src[d];
        __syncthreads();
        float val[4] = {0.f, 0.f, 0.f, 0.f};
        #pragma unroll
        for (int f = 0; f < F_; f++) {
            float wv = __ldg(&W[f * D_ + d]);
            #pragma unroll
            for (int r = 0; r < 4; r++) val[r] = fmaf(feat[r * F_ + f], wv, val[r]);
        }
        int lane = d & 31, w = d >> 5;
        #pragma unroll
        for (int r = 0; r < 4; r++) {
            float q = val[r] * val[r];
            #pragma unroll
            for (int o = 16; o; o >>= 1) q += __shfl_down_sync(0xffffffffu, q, o);
            if (lane == 0) spart[r * 8 + w] = q;
        }
        __syncthreads();
        if (d < 4) {
            float s = 0.f;
            #pragma unroll
            for (int i = 0; i < 8; i++) s += spart[d * 8 + i];
            sinv[d] = 1.0f / (sqrtf(s) + 1e-8f);
        }
        __syncthreads();
        #pragma unroll
        for (int r = 0; r < 4; r++) dst[r * D_ + d] = val[r] * sinv[r];
    } else {
        // ---- bucket vocab by length (warp-aggregated atomic slots) ----
        int pb = blk - (WB_ + UB_);
        int v = pb * 256 + d;
        bool act = v < V_;
        int len = act ? vlen[v] : 11;
        int idx = act ? (len - 4) : 7;
        int lane = d & 31;
        unsigned mask = __match_any_sync(0xffffffffu, idx);
        int leader = __ffs(mask) - 1;
        int prior = __popc(mask & ((1u << lane) - 1));
        int base = 0;
        if (lane == leader) base = atomicAdd(&g_cnt[idx], __popc(mask));
        base = __shfl_sync(mask, base, leader);
        if (act) {
            unsigned w[5];
            #pragma unroll
            for (int p = 0; p < 5; p++) {
                unsigned lo = (unsigned)segs[v * 10 + 2 * p];
                unsigned hi = (unsigned)segs[v * 10 + 2 * p + 1];
                w[p] = (lo & 0xFFFFu) | (hi << 16);
            }
            if (len <= 7) w[3] = (w[3] & 0xFFFFu) | ((unsigned)v << 16);  // v in spare slot
            int slot = idx * V_ + base + prior;
            g_segB[slot * 2]     = make_uint4(w[0], w[1], w[2], w[3]);
            g_segB[slot * 2 + 1] = make_uint4(w[4], (unsigned)v, 0u, 0u);
        }
        if (pb == PBK_ - 1) {
            if (d >= 32 && d < 48) g_keys[d - 32] = pack_key(NEGF, 0, 0);
            if (d == 63) g_done = 0u;
        }
    }
}

// ---------------------------------------------------------------------------
// Kernel 2: sim = wn @ un^T, 64x64 tile, FFMA2 with A duplicated in smem
// ({a,a} pairs -> no MOV duplication in the inner loop). K split in halves.
// grid = (10, 16, 2)
// ---------------------------------------------------------------------------
__global__ void __launch_bounds__(256) k_sim_gemm() {
    __shared__ float2 As2[16 * 64];   // {a, a} duplicated pairs
    __shared__ float  Bs[16 * 64];
    int tid = threadIdx.x;
    int n0 = blockIdx.x * 64;
    int m0 = blockIdx.y * 64;
    int kz = blockIdx.z;
    float* dst = g_sim + kz * (1024 * 600);
    int tx = tid & 15, ty = tid >> 4;
    int lm = tid >> 2;
    int lk = (tid & 3) * 4;
    unsigned long long acc2[4][2];
    #pragma unroll
    for (int i = 0; i < 4; i++) { acc2[i][0] = 0ull; acc2[i][1] = 0ull; }
    int kbeg = kz * 128;
    for (int k0 = kbeg; k0 < kbeg + 128; k0 += 16) {
        float4 a = *(const float4*)(g_wn + (m0 + lm) * 256 + k0 + lk);
        float4 bv = make_float4(0.f, 0.f, 0.f, 0.f);
        int n = n0 + lm;
        if (n < U_) bv = *(const float4*)(g_un + n * 256 + k0 + lk);
        __syncthreads();
        As2[(lk + 0) * 64 + lm] = make_float2(a.x, a.x);
        As2[(lk + 1) * 64 + lm] = make_float2(a.y, a.y);
        As2[(lk + 2) * 64 + lm] = make_float2(a.z, a.z);
        As2[(lk + 3) * 64 + lm] = make_float2(a.w, a.w);
        Bs[(lk + 0) * 64 + lm] = bv.x;
        Bs[(lk + 1) * 64 + lm] = bv.y;
        Bs[(lk + 2) * 64 + lm] = bv.z;
        Bs[(lk + 3) * 64 + lm] = bv.w;
        __syncthreads();
        #pragma unroll
        for (int kk = 0; kk < 16; kk++) {
            const ulonglong2* ap = (const ulonglong2*)(As2 + kk * 64 + ty * 4);
            ulonglong2 a01 = ap[0];          // {a0,a0},{a1,a1}
            ulonglong2 a23 = ap[1];          // {a2,a2},{a3,a3}
            ulonglong2 bp = *(const ulonglong2*)(Bs + kk * 64 + tx * 4);
            ffma2(acc2[0][0], a01.x, bp.x); ffma2(acc2[0][1], a01.x, bp.y);
            ffma2(acc2[1][0], a01.y, bp.x); ffma2(acc2[1][1], a01.y, bp.y);
            ffma2(acc2[2][0], a23.x, bp.x); ffma2(acc2[2][1], a23.x, bp.y);
            ffma2(acc2[3][0], a23.y, bp.x); ffma2(acc2[3][1], a23.y, bp.y);
        }
    }
    #pragma unroll
    for (int i = 0; i < 4; i++) {
        int m = m0 + ty * 4 + i;
        #pragma unroll
        for (int j2 = 0; j2 < 2; j2++) {
            float2 c = unpk2(acc2[i][j2]);
            int n = n0 + tx * 4 + j2 * 2;
            if (n < U_)     dst[m * U_ + n] = c.x;
            if (n + 1 < U_) dst[m * U_ + n + 1] = c.y;
        }
    }
}

// ---------------------------------------------------------------------------
// Kernel 3 (hot): CTA per (vc, b), 1024 threads (32 warps -> 50% occupancy).
// Smem: P[u*41 + r] = { sim[b][r][u], sim[b][r+32][u] }, rows>=64 are 0.
// Lanes = 32 start positions; both 32-l halves accumulated via f32x2.
// ---------------------------------------------------------------------------
#define PB_SMEM (600 * 41 * 8)
#define VC_ 9
#define NPART_ (VC_ * 32)       // 288 vocab partitions
#define NCTA_PB (VC_ * 16)      // 144

template<int LEN>
__device__ __forceinline__ void scan_bucket(
        const uint4* __restrict__ seg, int lo, int hi,
        const float2* __restrict__ Pl,
        unsigned long long midLo, unsigned long long midHi,
        bool okLo, bool okHi, float inv,
        unsigned long long& bestKey) {
    unsigned long long inv2 = pk2dup(inv);
    #pragma unroll 2
    for (int i = lo; i < hi; i++) {
        uint4 q0 = __ldg(&seg[2 * i]);
        unsigned u89 = 0, vv;
        if (LEN <= 7) {
            vv = q0.w >> 16;
        } else {
            uint4 q1 = __ldg(&seg[2 * i + 1]);
            u89 = q1.x; vv = q1.y;
        }
        unsigned long long acc;
        unsigned u;
        u = q0.x & 0xFFFFu;                 acc = *(const unsigned long long*)(Pl + u * 41 + 0);
        u = q0.x >> 16;                     fadd2(acc, *(const unsigned long long*)(Pl + u * 41 + 1));
        u = q0.y & 0xFFFFu;                 fadd2(acc, *(const unsigned long long*)(Pl + u * 41 + 2));
        u = q0.y >> 16;                     fadd2(acc, *(const unsigned long long*)(Pl + u * 41 + 3));
        if (LEN > 4) { u = q0.z & 0xFFFFu;  fadd2(acc, *(const unsigned long long*)(Pl + u * 41 + 4)); }
        if (LEN > 5) { u = q0.z >> 16;      fadd2(acc, *(const unsigned long long*)(Pl + u * 41 + 5)); }
        if (LEN > 6) { u = q0.w & 0xFFFFu;  fadd2(acc, *(const unsigned long long*)(Pl + u * 41 + 6)); }
        if (LEN > 7) { u = q0.w >> 16;      fadd2(acc, *(const unsigned long long*)(Pl + u * 41 + 7)); }
        if (LEN > 8) { u = u89 & 0xFFFFu;   fadd2(acc, *(const unsigned long long*)(Pl + u * 41 + 8)); }
        if (LEN > 9) { u = u89 >> 16;       fadd2(acc, *(const unsigned long long*)(Pl + u * 41 + 9)); }
        fmul2(acc, inv2);
        float2 s = unpk2(acc);
        unsigned long long vterm = (unsigned long long)(16383u - vv);
        if (okLo) {
            unsigned long long key = ((unsigned long long)f2mono(s.x) << 23) | midLo | vterm;
            if (key > bestKey) bestKey = key;
        }
        if (okHi) {
            unsigned long long key = ((unsigned long long)f2mono(s.y) << 23) | midHi | vterm;
            if (key > bestKey) bestKey = key;
        }
    }
}

__global__ void __launch_bounds__(1024, 1) k_phaseB(const int* __restrict__ lengths,
                                                    float* __restrict__ out) {
    extern __shared__ float2 P[];
    __shared__ int cnt_s[8];
    int vc = blockIdx.x;   // 0..8
    int b  = blockIdx.y;   // 0..15
    if (threadIdx.x < 8) cnt_s[threadIdx.x] = g_cnt[threadIdx.x];
    const float* sA = g_sim + b * 64 * U_;
    const float* sB = sA + 1024 * U_;
    for (int i = threadIdx.x; i < U_ * 41; i += 1024) {
        int r = i / U_;
        int u = i - r * U_;
        float lo = sA[r * U_ + u] + sB[r * U_ + u];
        float hi = (r < 32) ? (sA[(r + 32) * U_ + u] + sB[(r + 32) * U_ + u]) : 0.f;
        P[u * 41 + r] = make_float2(lo, hi);
    }
    __syncthreads();

    int warp = threadIdx.x >> 5;
    int lane = threadIdx.x & 31;
    int Lb = __ldg(&lengths[b]);
    const float2* Pl = P + lane;
    int part = vc * 32 + warp;
    unsigned long long bestKey = ((unsigned long long)f2mono(NEGF) << 23);

    #define DO_BUCKET(LI, LEN)                                                          \
    if (LEN <= Lb) {                                                                    \
        int n = cnt_s[LI];                                                              \
        int lo = (part * n) / NPART_;                                                   \
        int hi = ((part + 1) * n) / NPART_;                                             \
        bool okLo = lane + LEN <= Lb;                                                   \
        bool okHi = lane + 32 + LEN <= Lb;                                              \
        unsigned long long midLo = ((unsigned long long)(511 - (lane * E_ + LI)) << 14);\
        unsigned long long midHi = ((unsigned long long)(511 - ((lane + 32) * E_ + LI)) << 14);\
        scan_bucket<LEN>(g_segB + LI * (V_ * 2), lo, hi, Pl, midLo, midHi, okLo, okHi,  \
                         1.0f / (float)LEN, bestKey);                                   \
    }
    DO_BUCKET(0, 4) DO_BUCKET(1, 5) DO_BUCKET(2, 6) DO_BUCKET(3, 7)
    DO_BUCKET(4, 8) DO_BUCKET(5, 9) DO_BUCKET(6, 10)
    #undef DO_BUCKET

    #pragma unroll
    for (int o = 16; o; o >>= 1) {
        unsigned long long other = __shfl_down_sync(0xffffffffu, bestKey, o);
        if (other > bestKey) bestKey = other;
    }
    if (lane == 0) atomicMax(&g_keys[b], bestKey);

    // -------- fused epilogue: last CTA decodes + resets bucket counters -----
    __syncthreads();
    __threadfence();
    __shared__ unsigned s_old;
    if (threadIdx.x == 0) s_old = atomicAdd(&g_done, 1u);
    __syncthreads();
    if (s_old == NCTA_PB - 1) {
        int t = threadIdx.x;
        if (t < B_) {
            unsigned long long k2 = atomicAdd(&g_keys[t], 0ull);
            int v = 16383 - (int)(k2 & 0x3FFFull);
            int f = 511 - (int)((k2 >> 14) & 0x1FFull);
            unsigned mono = (unsigned)(k2 >> 23);
            unsigned fb = (mono & 0x80000000u) ? (mono & 0x7FFFFFFFu) : ~mono;
            float score = __uint_as_float(fb);
            int ll = f / E_;
            int e = f - ll * E_;
            out[0 * B_ + t] = score;
            out[1 * B_ + t] = (float)ll;
            out[2 * B_ + t] = (float)(ll + e + 3);
            out[3 * B_ + t] = (score > 0.05f) ? 1.0f : 0.0f;
            out[4 * B_ + t] = (float)v;
        }
        if (t >= 32 && t < 40) g_cnt[t - 32] = 0;   // ready for next replay
    }
}

// ---------------------------------------------------------------------------
extern "C" void kernel_launch(void* const* d_in, const int* in_sizes, int n_in,
                              void* d_out, int out_size) {
    const float* x       = (const float*)d_in[0];
    const float* uf      = (const float*)d_in[1];
    const float* W       = (const float*)d_in[2];
    const int*   lengths = (const int*)d_in[3];
    const int*   segs    = (const int*)d_in[4];
    const int*   vlen    = (const int*)d_in[5];
    float* out = (float*)d_out;

    cudaFuncSetAttribute(k_phaseB, cudaFuncAttributeMaxDynamicSharedMemorySize, PB_SMEM);

    k_setup<<<SETUP_GRID, 256>>>(x, uf, W, segs, vlen);
    k_sim_gemm<<<dim3(10, 16, 2), 256>>>();
    k_phaseB<<<dim3(VC_, B_), 1024, PB_SMEM>>>(lengths, out);
}

// round 11
// speedup vs baseline: 1.6968x; 1.1090x over previous
#include <cuda_runtime.h>
#include <cstdint>

#define B_  16
#define L_  64
#define F_  60
#define D_  256
#define U_  600
#define V_  10000
#define E_  7
#define NEGF (-1e9f)

// Scratch (device globals)
__device__ float g_wn[1024 * 256];
__device__ float g_un[600 * 256];
__device__ float g_sim[2 * 1024 * 600];      // two K-halves, summed in phaseB staging
__device__ uint4 g_segB[7 * V_ * 2];         // length-bucketed vocab
__device__ int   g_cnt[8];                   // bucket counts (zeroed by phaseB epilogue)
__device__ unsigned long long g_keys[16];
__device__ unsigned g_done;

// ---- f32x2 helpers ----
__device__ __forceinline__ void ffma2(unsigned long long& d, unsigned long long a, unsigned long long b) {
    asm("fma.rn.f32x2 %0, %1, %2, %0;" : "+l"(d) : "l"(a), "l"(b));
}
__device__ __forceinline__ void fadd2(unsigned long long& d, unsigned long long a) {
    asm("add.rn.f32x2 %0, %0, %1;" : "+l"(d) : "l"(a));
}
__device__ __forceinline__ void fmul2(unsigned long long& d, unsigned long long a) {
    asm("mul.rn.f32x2 %0, %0, %1;" : "+l"(d) : "l"(a));
}
__device__ __forceinline__ unsigned long long pk2dup(float a) {
    unsigned long long r; unsigned ai = __float_as_uint(a);
    asm("mov.b64 %0, {%1, %1};" : "=l"(r) : "r"(ai));
    return r;
}
__device__ __forceinline__ float2 unpk2(unsigned long long a) {
    unsigned lo, hi;
    asm("mov.b64 {%0, %1}, %2;" : "=r"(lo), "=r"(hi) : "l"(a));
    return make_float2(__uint_as_float(lo), __uint_as_float(hi));
}

__device__ __forceinline__ unsigned f2mono(float f) {
    unsigned b = __float_as_uint(f);
    return (b & 0x80000000u) ? ~b : (b | 0x80000000u);
}
__device__ __forceinline__ unsigned long long pack_key(float s, int f, int v) {
    return ((unsigned long long)f2mono(s) << 23)
         | ((unsigned long long)(511 - f) << 14)
         | (unsigned long long)(16383 - v);
}

// ---------------------------------------------------------------------------
// Kernel 1 (setup):
//   blocks   0..39  : vocab bucketing FIRST (atomics overlap embed compute)
//   blocks  40..295 : word rows  (256*4 = 1024)
//   blocks 296..445 : unit rows  (150*4 = 600)
// ---------------------------------------------------------------------------
#define PBK_ 40
#define WB_ 256
#define UB_ 150
#define SETUP_GRID (PBK_ + WB_ + UB_)   // 446

__global__ void __launch_bounds__(256) k_setup(const float* __restrict__ x,
                                               const float* __restrict__ uf,
                                               const float* __restrict__ W,
                                               const int* __restrict__ segs,
                                               const int* __restrict__ vlen) {
    int blk = blockIdx.x;
    int d = threadIdx.x;               // 0..255
    if (blk >= PBK_) {
        // ---- embed 4 rows/block, direct W loads ----
        __shared__ float feat[4 * F_];
        __shared__ float spart[4 * 8];
        __shared__ float sinv[4];
        int eb = blk - PBK_;
        bool isWord = eb < WB_;
        int r0 = isWord ? eb * 4 : (eb - WB_) * 4;
        const float* src = isWord ? (x + r0 * F_) : (uf + r0 * F_);
        float* dst = isWord ? (g_wn + r0 * D_) : (g_un + r0 * D_);
        if (d < 60) ((float4*)feat)[d] = ((const float4*)src)[d];  // 240 floats
        __syncthreads();
        float val[4] = {0.f, 0.f, 0.f, 0.f};
        #pragma unroll
        for (int f = 0; f < F_; f++) {
            float wv = __ldg(&W[f * D_ + d]);
            #pragma unroll
            for (int r = 0; r < 4; r++) val[r] = fmaf(feat[r * F_ + f], wv, val[r]);
        }
        int lane = d & 31, w = d >> 5;
        #pragma unroll
        for (int r = 0; r < 4; r++) {
            float q = val[r] * val[r];
            #pragma unroll
            for (int o = 16; o; o >>= 1) q += __shfl_down_sync(0xffffffffu, q, o);
            if (lane == 0) spart[r * 8 + w] = q;
        }
        __syncthreads();
        if (d < 4) {
            float s = 0.f;
            #pragma unroll
            for (int i = 0; i < 8; i++) s += spart[d * 8 + i];
            sinv[d] = 1.0f / (sqrtf(s) + 1e-8f);
        }
        __syncthreads();
        #pragma unroll
        for (int r = 0; r < 4; r++) dst[r * D_ + d] = val[r] * sinv[r];
    } else {
        // ---- bucket vocab by length: block-aggregated atomics ----
        __shared__ int blkCnt[8];
        __shared__ int blkBase[8];
        int pb = blk;
        int v = pb * 256 + d;
        bool act = v < V_;
        if (d < 8) blkCnt[d] = 0;
        __syncthreads();
        int len = act ? vlen[v] : 11;
        int idx = act ? (len - 4) : 7;
        int lane = d & 31;
        unsigned mask = __match_any_sync(0xffffffffu, idx);
        int leader = __ffs(mask) - 1;
        int prior = __popc(mask & ((1u << lane) - 1));
        int wbase = 0;
        if (lane == leader) wbase = atomicAdd(&blkCnt[idx], __popc(mask));
        wbase = __shfl_sync(mask, wbase, leader);
        int local = wbase + prior;
        __syncthreads();
        if (d < 8) blkBase[d] = atomicAdd(&g_cnt[d], blkCnt[d]);   // 8 global atomics/block
        __syncthreads();
        if (act) {
            unsigned w[5];
            #pragma unroll
            for (int p = 0; p < 5; p++) {
                unsigned lo = (unsigned)segs[v * 10 + 2 * p];
                unsigned hi = (unsigned)segs[v * 10 + 2 * p + 1];
                w[p] = (lo & 0xFFFFu) | (hi << 16);
            }
            if (len <= 7) w[3] = (w[3] & 0xFFFFu) | ((unsigned)v << 16);  // v in spare slot
            int slot = idx * V_ + blkBase[idx] + local;
            g_segB[slot * 2]     = make_uint4(w[0], w[1], w[2], w[3]);
            g_segB[slot * 2 + 1] = make_uint4(w[4], (unsigned)v, 0u, 0u);
        }
        if (pb == 0) {
            if (d >= 32 && d < 48) g_keys[d - 32] = pack_key(NEGF, 0, 0);
            if (d == 63) g_done = 0u;
        }
    }
}

// ---------------------------------------------------------------------------
// Kernel 2: sim = wn @ un^T.  128x64 tile, 256 threads, 8x4 per-thread
// register tile, FFMA2 (a duplicated in regs, b as smem pairs).
// 3 LDS.128 per 32 FMAs.  K split in halves.  grid = (10, 8, 2) = 160 CTAs.
// ---------------------------------------------------------------------------
__global__ void __launch_bounds__(256) k_sim_gemm() {
    __shared__ float As[16][128];   // [k][m]
    __shared__ float Bs[16][64];    // [k][n]
    int tid = threadIdx.x;
    int n0 = blockIdx.x * 64;
    int m0 = blockIdx.y * 128;
    int kz = blockIdx.z;
    float* dst = g_sim + kz * (1024 * 600);
    int tx = tid & 15;              // n-group (16 x 4 = 64)
    int ty = tid >> 4;              // m-group (16 x 8 = 128)
    // loader indices
    int am = tid >> 1;              // 0..127
    int ak = (tid & 1) * 8;         // k-offset 0 or 8 (two float4 each)
    int bn = tid >> 2;              // 0..63
    int bk = (tid & 3) * 4;         // k-offset 0,4,8,12
    bool bok = (n0 + bn) < U_;

    unsigned long long acc2[8][2];
    #pragma unroll
    for (int i = 0; i < 8; i++) { acc2[i][0] = 0ull; acc2[i][1] = 0ull; }

    int kbeg = kz * 128;
    for (int k0 = kbeg; k0 < kbeg + 128; k0 += 16) {
        float4 a0 = *(const float4*)(g_wn + (m0 + am) * 256 + k0 + ak);
        float4 a1 = *(const float4*)(g_wn + (m0 + am) * 256 + k0 + ak + 4);
        float4 bv = make_float4(0.f, 0.f, 0.f, 0.f);
        if (bok) bv = *(const float4*)(g_un + (n0 + bn) * 256 + k0 + bk);
        __syncthreads();
        As[ak + 0][am] = a0.x; As[ak + 1][am] = a0.y;
        As[ak + 2][am] = a0.z; As[ak + 3][am] = a0.w;
        As[ak + 4][am] = a1.x; As[ak + 5][am] = a1.y;
        As[ak + 6][am] = a1.z; As[ak + 7][am] = a1.w;
        Bs[bk + 0][bn] = bv.x; Bs[bk + 1][bn] = bv.y;
        Bs[bk + 2][bn] = bv.z; Bs[bk + 3][bn] = bv.w;
        __syncthreads();
        #pragma unroll
        for (int kk = 0; kk < 16; kk++) {
            float4 av0 = *(const float4*)&As[kk][ty * 8];
            float4 av1 = *(const float4*)&As[kk][ty * 8 + 4];
            ulonglong2 bp = *(const ulonglong2*)&Bs[kk][tx * 4];
            unsigned long long d0 = pk2dup(av0.x), d1 = pk2dup(av0.y);
            unsigned long long d2 = pk2dup(av0.z), d3 = pk2dup(av0.w);
            unsigned long long d4 = pk2dup(av1.x), d5 = pk2dup(av1.y);
            unsigned long long d6 = pk2dup(av1.z), d7 = pk2dup(av1.w);
            ffma2(acc2[0][0], d0, bp.x); ffma2(acc2[0][1], d0, bp.y);
            ffma2(acc2[1][0], d1, bp.x); ffma2(acc2[1][1], d1, bp.y);
            ffma2(acc2[2][0], d2, bp.x); ffma2(acc2[2][1], d2, bp.y);
            ffma2(acc2[3][0], d3, bp.x); ffma2(acc2[3][1], d3, bp.y);
            ffma2(acc2[4][0], d4, bp.x); ffma2(acc2[4][1], d4, bp.y);
            ffma2(acc2[5][0], d5, bp.x); ffma2(acc2[5][1], d5, bp.y);
            ffma2(acc2[6][0], d6, bp.x); ffma2(acc2[6][1], d6, bp.y);
            ffma2(acc2[7][0], d7, bp.x); ffma2(acc2[7][1], d7, bp.y);
        }
    }
    #pragma unroll
    for (int i = 0; i < 8; i++) {
        int m = m0 + ty * 8 + i;
        #pragma unroll
        for (int j2 = 0; j2 < 2; j2++) {
            float2 c = unpk2(acc2[i][j2]);
            int n = n0 + tx * 4 + j2 * 2;
            if (n < U_)     dst[m * U_ + n] = c.x;
            if (n + 1 < U_) dst[m * U_ + n + 1] = c.y;
        }
    }
}

// ---------------------------------------------------------------------------
// Kernel 3 (hot): CTA per (vc, b), 1024 threads (32 warps -> 50% occupancy).
// Smem: P[u*41 + r] = { sim[b][r][u], sim[b][r+32][u] }, rows>=64 are 0.
// Lanes = 32 start positions; both 32-l halves accumulated via f32x2.
// ---------------------------------------------------------------------------
#define PB_SMEM (600 * 41 * 8)
#define VC_ 9
#define NPART_ (VC_ * 32)       // 288 vocab partitions
#define NCTA_PB (VC_ * 16)      // 144

template<int LEN>
__device__ __forceinline__ void scan_bucket(
        const uint4* __restrict__ seg, int lo, int hi,
        const float2* __restrict__ Pl,
        unsigned long long midLo, unsigned long long midHi,
        bool okLo, bool okHi, float inv,
        unsigned long long& bestKey) {
    unsigned long long inv2 = pk2dup(inv);
    #pragma unroll 2
    for (int i = lo; i < hi; i++) {
        uint4 q0 = __ldg(&seg[2 * i]);
        unsigned u89 = 0, vv;
        if (LEN <= 7) {
            vv = q0.w >> 16;
        } else {
            uint4 q1 = __ldg(&seg[2 * i + 1]);
            u89 = q1.x; vv = q1.y;
        }
        unsigned long long acc;
        unsigned u;
        u = q0.x & 0xFFFFu;                 acc = *(const unsigned long long*)(Pl + u * 41 + 0);
        u = q0.x >> 16;                     fadd2(acc, *(const unsigned long long*)(Pl + u * 41 + 1));
        u = q0.y & 0xFFFFu;                 fadd2(acc, *(const unsigned long long*)(Pl + u * 41 + 2));
        u = q0.y >> 16;                     fadd2(acc, *(const unsigned long long*)(Pl + u * 41 + 3));
        if (LEN > 4) { u = q0.z & 0xFFFFu;  fadd2(acc, *(const unsigned long long*)(Pl + u * 41 + 4)); }
        if (LEN > 5) { u = q0.z >> 16;      fadd2(acc, *(const unsigned long long*)(Pl + u * 41 + 5)); }
        if (LEN > 6) { u = q0.w & 0xFFFFu;  fadd2(acc, *(const unsigned long long*)(Pl + u * 41 + 6)); }
        if (LEN > 7) { u = q0.w >> 16;      fadd2(acc, *(const unsigned long long*)(Pl + u * 41 + 7)); }
        if (LEN > 8) { u = u89 & 0xFFFFu;   fadd2(acc, *(const unsigned long long*)(Pl + u * 41 + 8)); }
        if (LEN > 9) { u = u89 >> 16;       fadd2(acc, *(const unsigned long long*)(Pl + u * 41 + 9)); }
        fmul2(acc, inv2);
        float2 s = unpk2(acc);
        unsigned long long vterm = (unsigned long long)(16383u - vv);
        if (okLo) {
            unsigned long long key = ((unsigned long long)f2mono(s.x) << 23) | midLo | vterm;
            if (key > bestKey) bestKey = key;
        }
        if (okHi) {
            unsigned long long key = ((unsigned long long)f2mono(s.y) << 23) | midHi | vterm;
            if (key > bestKey) bestKey = key;
        }
    }
}

__global__ void __launch_bounds__(1024, 1) k_phaseB(const int* __restrict__ lengths,
                                                    float* __restrict__ out) {
    extern __shared__ float2 P[];
    __shared__ int cnt_s[8];
    int vc = blockIdx.x;   // 0..8
    int b  = blockIdx.y;   // 0..15
    if (threadIdx.x < 8) cnt_s[threadIdx.x] = g_cnt[threadIdx.x];
    const float* sA = g_sim + b * 64 * U_;
    const float* sB = sA + 1024 * U_;
    for (int i = threadIdx.x; i < U_ * 41; i += 1024) {
        int r = i / U_;
        int u = i - r * U_;
        float lo = sA[r * U_ + u] + sB[r * U_ + u];
        float hi = (r < 32) ? (sA[(r + 32) * U_ + u] + sB[(r + 32) * U_ + u]) : 0.f;
        P[u * 41 + r] = make_float2(lo, hi);
    }
    __syncthreads();

    int warp = threadIdx.x >> 5;
    int lane = threadIdx.x & 31;
    int Lb = __ldg(&lengths[b]);
    const float2* Pl = P + lane;
    int part = vc * 32 + warp;
    unsigned long long bestKey = ((unsigned long long)f2mono(NEGF) << 23);

    #define DO_BUCKET(LI, LEN)                                                          \
    if (LEN <= Lb) {                                                                    \
        int n = cnt_s[LI];                                                              \
        int lo = (part * n) / NPART_;                                                   \
        int hi = ((part + 1) * n) / NPART_;                                             \
        bool okLo = lane + LEN <= Lb;                                                   \
        bool okHi = lane + 32 + LEN <= Lb;                                              \
        unsigned long long midLo = ((unsigned long long)(511 - (lane * E_ + LI)) << 14);\
        unsigned long long midHi = ((unsigned long long)(511 - ((lane + 32) * E_ + LI)) << 14);\
        scan_bucket<LEN>(g_segB + LI * (V_ * 2), lo, hi, Pl, midLo, midHi, okLo, okHi,  \
                         1.0f / (float)LEN, bestKey);                                   \
    }
    DO_BUCKET(0, 4) DO_BUCKET(1, 5) DO_BUCKET(2, 6) DO_BUCKET(3, 7)
    DO_BUCKET(4, 8) DO_BUCKET(5, 9) DO_BUCKET(6, 10)
    #undef DO_BUCKET

    #pragma unroll
    for (int o = 16; o; o >>= 1) {
        unsigned long long other = __shfl_down_sync(0xffffffffu, bestKey, o);
        if (other > bestKey) bestKey = other;
    }
    if (lane == 0) atomicMax(&g_keys[b], bestKey);

    // -------- fused epilogue: last CTA decodes + resets bucket counters -----
    __syncthreads();
    __threadfence();
    __shared__ unsigned s_old;
    if (threadIdx.x == 0) s_old = atomicAdd(&g_done, 1u);
    __syncthreads();
    if (s_old == NCTA_PB - 1) {
        int t = threadIdx.x;
        if (t < B_) {
            unsigned long long k2 = atomicAdd(&g_keys[t], 0ull);
            int v = 16383 - (int)(k2 & 0x3FFFull);
            int f = 511 - (int)((k2 >> 14) & 0x1FFull);
            unsigned mono = (unsigned)(k2 >> 23);
            unsigned fb = (mono & 0x80000000u) ? (mono & 0x7FFFFFFFu) : ~mono;
            float score = __uint_as_float(fb);
            int ll = f / E_;
            int e = f - ll * E_;
            out[0 * B_ + t] = score;
            out[1 * B_ + t] = (float)ll;
            out[2 * B_ + t] = (float)(ll + e + 3);
            out[3 * B_ + t] = (score > 0.05f) ? 1.0f : 0.0f;
            out[4 * B_ + t] = (float)v;
        }
        if (t >= 32 && t < 40) g_cnt[t - 32] = 0;   // ready for next replay
    }
}

// ---------------------------------------------------------------------------
extern "C" void kernel_launch(void* const* d_in, const int* in_sizes, int n_in,
                              void* d_out, int out_size) {
    const float* x       = (const float*)d_in[0];
    const float* uf      = (const float*)d_in[1];
    const float* W       = (const float*)d_in[2];
    const int*   lengths = (const int*)d_in[3];
    const int*   segs    = (const int*)d_in[4];
    const int*   vlen    = (const int*)d_in[5];
    float* out = (float*)d_out;

    cudaFuncSetAttribute(k_phaseB, cudaFuncAttributeMaxDynamicSharedMemorySize, PB_SMEM);

    k_setup<<<SETUP_GRID, 256>>>(x, uf, W, segs, vlen);
    k_sim_gemm<<<dim3(10, 8, 2), 256>>>();
    k_phaseB<<<dim3(VC_, B_), 1024, PB_SMEM>>>(lengths, out);
}